// round 3
// baseline (speedup 1.0000x reference)
#include <cuda_runtime.h>
#include <cuda_bf16.h>

// DiffJPEG: per-8x8-block  D X D^T -> round(./Q)*Q -> D^T Y D
// Input/output: (32, 3, 512, 512) float32.
//
// 8 threads per 8x8 block (lane owns one row; 4 blocks per warp, lane = r*4+b).
// Row transforms are register-local butterflies (36 fma-ops per 8-pt DCT);
// column transforms become row transforms after a 3-stage shfl.bfly transpose.
// ~40 regs/thread -> high occupancy to saturate HBM.

static constexpr int IMG_W    = 512;
static constexpr int IMG_H    = 512;
static constexpr int NCHAN    = 32 * 3;                  // flattened B*C
static constexpr int BLK_X    = IMG_W / 8;               // 64
static constexpr int BLK_Y    = IMG_H / 8;               // 64
static constexpr int NBLOCKS  = NCHAN * BLK_Y * BLK_X;   // 393216
static constexpr int TPB      = 128;
static constexpr int BLOCKS_PER_CTA = TPB / 8;           // 16

// half-cosine constants: Hk = 0.5*cos(k*pi/16); A0 = sqrt(1/8)
#define H1 0.49039264020161522f
#define H2 0.46193976625564337f
#define H3 0.41573480615127262f
#define H5 0.27778511650980114f
#define H6 0.19134171618254492f
#define H7 0.097545161008064166f
#define A0 0.35355339059327373f

// Q^T (column-major JPEG luma table @ quality 50) and its reciprocal, so
// lane p (holding DCT column p) reads a contiguous float4 pair (row p).
__device__ const float c_QT[64] = {
    16, 12, 14, 14, 18, 24, 49, 72,
    11, 12, 13, 17, 22, 35, 64, 92,
    10, 14, 16, 22, 37, 55, 78, 95,
    16, 19, 24, 29, 56, 64, 87, 98,
    24, 26, 40, 51, 68, 81, 103, 112,
    40, 58, 57, 87, 109, 104, 121, 100,
    51, 60, 69, 80, 103, 113, 120, 103,
    61, 55, 56, 62, 77, 92, 101, 99,
};
__device__ const float c_QIT[64] = {
    1.0f/16, 1.0f/12, 1.0f/14, 1.0f/14, 1.0f/18, 1.0f/24, 1.0f/49, 1.0f/72,
    1.0f/11, 1.0f/12, 1.0f/13, 1.0f/17, 1.0f/22, 1.0f/35, 1.0f/64, 1.0f/92,
    1.0f/10, 1.0f/14, 1.0f/16, 1.0f/22, 1.0f/37, 1.0f/55, 1.0f/78, 1.0f/95,
    1.0f/16, 1.0f/19, 1.0f/24, 1.0f/29, 1.0f/56, 1.0f/64, 1.0f/87, 1.0f/98,
    1.0f/24, 1.0f/26, 1.0f/40, 1.0f/51, 1.0f/68, 1.0f/81, 1.0f/103, 1.0f/112,
    1.0f/40, 1.0f/58, 1.0f/57, 1.0f/87, 1.0f/109, 1.0f/104, 1.0f/121, 1.0f/100,
    1.0f/51, 1.0f/60, 1.0f/69, 1.0f/80, 1.0f/103, 1.0f/113, 1.0f/120, 1.0f/103,
    1.0f/61, 1.0f/55, 1.0f/56, 1.0f/62, 1.0f/77, 1.0f/92, 1.0f/101, 1.0f/99,
};

// Forward 8-pt DCT-II, in place.
__device__ __forceinline__ void dct8(float v[8])
{
    const float s0 = v[0] + v[7], s1 = v[1] + v[6];
    const float s2 = v[2] + v[5], s3 = v[3] + v[4];
    const float d0 = v[0] - v[7], d1 = v[1] - v[6];
    const float d2 = v[2] - v[5], d3 = v[3] - v[4];

    const float e0 = s0 + s3, e1 = s1 + s2;
    const float f0 = s0 - s3, f1 = s1 - s2;

    v[0] = A0 * (e0 + e1);
    v[4] = A0 * (e0 - e1);
    v[2] = fmaf(H2, f0,  H6 * f1);
    v[6] = fmaf(H6, f0, -H2 * f1);

    v[1] = fmaf(H1, d0, fmaf( H3, d1, fmaf( H5, d2,  H7 * d3)));
    v[3] = fmaf(H3, d0, fmaf(-H7, d1, fmaf(-H1, d2, -H5 * d3)));
    v[5] = fmaf(H5, d0, fmaf(-H1, d1, fmaf( H7, d2,  H3 * d3)));
    v[7] = fmaf(H7, d0, fmaf(-H5, d1, fmaf( H3, d2, -H1 * d3)));
}

// Inverse (DCT-III = D^T), in place.
__device__ __forceinline__ void idct8(float v[8])
{
    const float p = A0 * (v[0] + v[4]);
    const float q = A0 * (v[0] - v[4]);
    const float r = fmaf(H2, v[2],  H6 * v[6]);
    const float s = fmaf(H6, v[2], -H2 * v[6]);

    const float E0 = p + r, E1 = q + s, E2 = q - s, E3 = p - r;

    const float O0 = fmaf(H1, v[1], fmaf( H3, v[3], fmaf( H5, v[5],  H7 * v[7])));
    const float O1 = fmaf(H3, v[1], fmaf(-H7, v[3], fmaf(-H1, v[5], -H5 * v[7])));
    const float O2 = fmaf(H5, v[1], fmaf(-H1, v[3], fmaf( H7, v[5],  H3 * v[7])));
    const float O3 = fmaf(H7, v[1], fmaf(-H5, v[3], fmaf( H3, v[5], -H1 * v[7])));

    v[0] = E0 + O0;  v[7] = E0 - O0;
    v[1] = E1 + O1;  v[6] = E1 - O1;
    v[2] = E2 + O2;  v[5] = E2 - O2;
    v[3] = E3 + O3;  v[4] = E3 - O3;
}

// 8x8 transpose across lanes (lane = r*4 + b, stride 4 within warp).
// 3 bfly stages; register bit s pairs with lane bit s<<2.
__device__ __forceinline__ void transpose8(float v[8], int lane)
{
#pragma unroll
    for (int s = 1; s < 8; s <<= 1) {
        const int  lm = s << 2;
        const bool up = (lane & lm) != 0;
#pragma unroll
        for (int j = 0; j < 8; ++j) {
            if ((j & s) == 0) {
                const float a = v[j], b = v[j | s];
                float t = up ? a : b;
                t = __shfl_xor_sync(0xffffffffu, t, lm);
                if (up) v[j] = t; else v[j | s] = t;
            }
        }
    }
}

__global__ void __launch_bounds__(TPB) diffjpeg_kernel(
    const float* __restrict__ in, float* __restrict__ out)
{
    const int lane = threadIdx.x & 31;
    const int b    = lane & 3;            // block within warp's group of 4
    const int r    = lane >> 2;           // row within block

    const int warpg = (blockIdx.x * TPB + threadIdx.x) >> 5;  // global warp id
    const int blk   = warpg * 4 + b;                          // global 8x8 block id

    const int bx  = blk & (BLK_X - 1);
    const int t2  = blk >> 6;
    const int by  = t2 & (BLK_Y - 1);
    const int ch  = t2 >> 6;

    // byte-exact 32-bit element offset (total 25.2M elements < 2^31)
    const int off = ((ch * IMG_H + by * 8 + r) * IMG_W) + bx * 8;

    // ---- load row r of the block (2x float4; warp touches 8 full lines) ----
    float v[8];
    {
        const float4 va = *reinterpret_cast<const float4*>(in + off);
        const float4 vb = *reinterpret_cast<const float4*>(in + off + 4);
        v[0] = va.x; v[1] = va.y; v[2] = va.z; v[3] = va.w;
        v[4] = vb.x; v[5] = vb.y; v[6] = vb.z; v[7] = vb.w;
    }

    // ---- 2D forward DCT ----
    dct8(v);                 // along rows:    X D^T
    transpose8(v, lane);     // lane p now holds column p
    dct8(v);                 // along cols:    lane p = (D X D^T)[.,p]

    // ---- quantize + dequantize (round half-to-even == jnp.round) ----
    {
        const float4 qi0 = *reinterpret_cast<const float4*>(c_QIT + r * 8);
        const float4 qi1 = *reinterpret_cast<const float4*>(c_QIT + r * 8 + 4);
        const float4 q0  = *reinterpret_cast<const float4*>(c_QT  + r * 8);
        const float4 q1  = *reinterpret_cast<const float4*>(c_QT  + r * 8 + 4);
        v[0] = rintf(v[0] * qi0.x) * q0.x;
        v[1] = rintf(v[1] * qi0.y) * q0.y;
        v[2] = rintf(v[2] * qi0.z) * q0.z;
        v[3] = rintf(v[3] * qi0.w) * q0.w;
        v[4] = rintf(v[4] * qi1.x) * q1.x;
        v[5] = rintf(v[5] * qi1.y) * q1.y;
        v[6] = rintf(v[6] * qi1.z) * q1.z;
        v[7] = rintf(v[7] * qi1.w) * q1.w;
    }

    // ---- 2D inverse DCT ----
    idct8(v);                // D^T along cols (local on lane p's vector)
    transpose8(v, lane);     // back to rows
    idct8(v);                // along rows: W D

    // ---- store row r ----
    float4 va, vb;
    va.x = v[0]; va.y = v[1]; va.z = v[2]; va.w = v[3];
    vb.x = v[4]; vb.y = v[5]; vb.z = v[6]; vb.w = v[7];
    *reinterpret_cast<float4*>(out + off)     = va;
    *reinterpret_cast<float4*>(out + off + 4) = vb;
}

extern "C" void kernel_launch(void* const* d_in, const int* in_sizes, int n_in,
                              void* d_out, int out_size)
{
    const float* img = (const float*)d_in[0];
    float* out = (float*)d_out;
    diffjpeg_kernel<<<NBLOCKS / BLOCKS_PER_CTA, TPB>>>(img, out);
}

// round 4
// speedup vs baseline: 1.1763x; 1.1763x over previous
#include <cuda_runtime.h>
#include <cuda_bf16.h>

// DiffJPEG: per-8x8-block  D X D^T -> round(./Q)*Q -> D^T Y D
// Input/output: (32, 3, 512, 512) float32. One thread owns one 8x8 block.
//
// All transform arithmetic is packed f32x2 (2 lanes per instruction):
//  - column transforms pack adjacent columns (natural layout from LDG.128)
//  - row transforms pack adjacent rows (one register repack between phases)
//  - quantization rounding uses the exact RNE magic-add, packed too.
// ~704 packed fma-pipe ops per 64-element block vs ~1150 scalar before.

typedef unsigned long long u64;

static constexpr int IMG_W    = 512;
static constexpr int IMG_H    = 512;
static constexpr int BLK_X    = IMG_W / 8;               // 64
static constexpr int BLK_Y    = IMG_H / 8;               // 64
static constexpr int NBLOCKS  = 96 * BLK_Y * BLK_X;      // 393216
static constexpr int TPB      = 128;

// half-cosine constants: Hk = 0.5*cos(k*pi/16); A0 = sqrt(1/8)
#define H1 0.49039264020161522f
#define H2 0.46193976625564337f
#define H3 0.41573480615127262f
#define H5 0.27778511650980114f
#define H6 0.19134171618254492f
#define H7 0.097545161008064166f
#define A0 0.35355339059327373f

// ---- packed f32x2 primitives (inline PTX; sm_100 native) ----
__device__ __forceinline__ u64 add2(u64 a, u64 b) {
    u64 d; asm("add.rn.f32x2 %0,%1,%2;" : "=l"(d) : "l"(a), "l"(b)); return d;
}
__device__ __forceinline__ u64 sub2(u64 a, u64 b) {
    u64 d; asm("sub.rn.f32x2 %0,%1,%2;" : "=l"(d) : "l"(a), "l"(b)); return d;
}
__device__ __forceinline__ u64 mul2(u64 a, u64 b) {
    u64 d; asm("mul.rn.f32x2 %0,%1,%2;" : "=l"(d) : "l"(a), "l"(b)); return d;
}
__device__ __forceinline__ u64 fma2(u64 a, u64 b, u64 c) {
    u64 d; asm("fma.rn.f32x2 %0,%1,%2,%3;" : "=l"(d) : "l"(a), "l"(b), "l"(c)); return d;
}
// pack/unpack (register-pair moves; land on the idle alu pipe)
__device__ __forceinline__ u64 pk(float lo, float hi) {
    u64 d; asm("mov.b64 %0,{%1,%2};" : "=l"(d) : "f"(lo), "f"(hi)); return d;
}
__device__ __forceinline__ void upk(u64 v, float& lo, float& hi) {
    asm("mov.b64 {%0,%1},%2;" : "=f"(lo), "=f"(hi) : "l"(v));
}
// compile-time packed constants
__device__ __forceinline__ u64 C2(float lo, float hi) {
    return ((u64)__float_as_uint(hi) << 32) | (u64)__float_as_uint(lo);
}
__device__ __forceinline__ u64 CD(float c) { return C2(c, c); }

// Forward 8-pt DCT-II on a packed pair of sequences, in place.
__device__ __forceinline__ void dct8p(u64 v[8])
{
    const u64 s0 = add2(v[0], v[7]), s1 = add2(v[1], v[6]);
    const u64 s2 = add2(v[2], v[5]), s3 = add2(v[3], v[4]);
    const u64 d0 = sub2(v[0], v[7]), d1 = sub2(v[1], v[6]);
    const u64 d2 = sub2(v[2], v[5]), d3 = sub2(v[3], v[4]);

    const u64 e0 = add2(s0, s3), e1 = add2(s1, s2);
    const u64 f0 = sub2(s0, s3), f1 = sub2(s1, s2);

    v[0] = mul2(CD(A0), add2(e0, e1));
    v[4] = mul2(CD(A0), sub2(e0, e1));
    v[2] = fma2(CD(H2), f0, mul2(CD( H6), f1));
    v[6] = fma2(CD(H6), f0, mul2(CD(-H2), f1));

    v[1] = fma2(CD(H1), d0, fma2(CD( H3), d1, fma2(CD( H5), d2, mul2(CD( H7), d3))));
    v[3] = fma2(CD(H3), d0, fma2(CD(-H7), d1, fma2(CD(-H1), d2, mul2(CD(-H5), d3))));
    v[5] = fma2(CD(H5), d0, fma2(CD(-H1), d1, fma2(CD( H7), d2, mul2(CD( H3), d3))));
    v[7] = fma2(CD(H7), d0, fma2(CD(-H5), d1, fma2(CD( H3), d2, mul2(CD(-H1), d3))));
}

// Inverse (DCT-III = D^T), packed, in place.
__device__ __forceinline__ void idct8p(u64 v[8])
{
    const u64 p = mul2(CD(A0), add2(v[0], v[4]));
    const u64 q = mul2(CD(A0), sub2(v[0], v[4]));
    const u64 r = fma2(CD(H2), v[2], mul2(CD( H6), v[6]));
    const u64 s = fma2(CD(H6), v[2], mul2(CD(-H2), v[6]));

    const u64 E0 = add2(p, r), E1 = add2(q, s);
    const u64 E2 = sub2(q, s), E3 = sub2(p, r);

    const u64 O0 = fma2(CD(H1), v[1], fma2(CD( H3), v[3], fma2(CD( H5), v[5], mul2(CD( H7), v[7]))));
    const u64 O1 = fma2(CD(H3), v[1], fma2(CD(-H7), v[3], fma2(CD(-H1), v[5], mul2(CD(-H5), v[7]))));
    const u64 O2 = fma2(CD(H5), v[1], fma2(CD(-H1), v[3], fma2(CD( H7), v[5], mul2(CD( H3), v[7]))));
    const u64 O3 = fma2(CD(H7), v[1], fma2(CD(-H5), v[3], fma2(CD( H3), v[5], mul2(CD(-H1), v[7]))));

    v[0] = add2(E0, O0);  v[7] = sub2(E0, O0);
    v[1] = add2(E1, O1);  v[6] = sub2(E1, O1);
    v[2] = add2(E2, O2);  v[5] = sub2(E2, O2);
    v[3] = add2(E3, O3);  v[4] = sub2(E3, O3);
}

__global__ void __launch_bounds__(TPB, 5) diffjpeg_kernel(
    const float* __restrict__ in, float* __restrict__ out)
{
    const int bid = blockIdx.x * TPB + threadIdx.x;
    const int bx  = bid & (BLK_X - 1);
    const int t2  = bid >> 6;
    const int by  = t2 & (BLK_Y - 1);
    const int ch  = t2 >> 6;

    const size_t base = ((size_t)ch * IMG_H + (size_t)by * 8) * IMG_W + (size_t)bx * 8;

    // JPEG luma table @ quality 50 (== base table)
    const float Qt[8][8] = {
        {16, 11, 10, 16, 24, 40, 51, 61},
        {12, 12, 14, 19, 26, 58, 60, 55},
        {14, 13, 16, 24, 40, 57, 69, 56},
        {14, 17, 22, 29, 51, 87, 80, 62},
        {18, 22, 37, 56, 68, 109, 103, 77},
        {24, 35, 55, 64, 81, 104, 113, 92},
        {49, 64, 78, 87, 103, 121, 120, 101},
        {72, 92, 95, 98, 112, 100, 103, 99},
    };

    // ---- load: A[i][c] = (x[i][2c], x[i][2c+1])  (2x LDG.128 per row) ----
    u64 A[8][4];
#pragma unroll
    for (int i = 0; i < 8; ++i) {
        const ulonglong2* pr = reinterpret_cast<const ulonglong2*>(in + base + (size_t)i * IMG_W);
        const ulonglong2 va = pr[0];
        const ulonglong2 vb = pr[1];
        A[i][0] = va.x; A[i][1] = va.y; A[i][2] = vb.x; A[i][3] = vb.y;
    }

    // ---- column DCT (transform across i; columns packed in pairs) ----
#pragma unroll
    for (int c = 0; c < 4; ++c) {
        u64 v[8];
#pragma unroll
        for (int i = 0; i < 8; ++i) v[i] = A[i][c];
        dct8p(v);
#pragma unroll
        for (int i = 0; i < 8; ++i) A[i][c] = v[i];
    }

    // ---- repack A -> B:  B[j][p] = (y[2p][j], y[2p+1][j]) ----
    float xf[8][8];
#pragma unroll
    for (int i = 0; i < 8; ++i)
#pragma unroll
        for (int c = 0; c < 4; ++c) upk(A[i][c], xf[i][2 * c], xf[i][2 * c + 1]);

    u64 B[8][4];
#pragma unroll
    for (int j = 0; j < 8; ++j)
#pragma unroll
        for (int p = 0; p < 4; ++p) B[j][p] = pk(xf[2 * p][j], xf[2 * p + 1][j]);

    // ---- row DCT (transform across j; rows packed in pairs) ----
#pragma unroll
    for (int p = 0; p < 4; ++p) {
        u64 v[8];
#pragma unroll
        for (int j = 0; j < 8; ++j) v[j] = B[j][p];
        dct8p(v);
#pragma unroll
        for (int j = 0; j < 8; ++j) B[j][p] = v[j];
    }

    // ---- quantize + dequantize: packed, exact round-half-even magic-add ----
    {
        const u64 MAGIC = CD(12582912.0f);  // 1.5 * 2^23
#pragma unroll
        for (int j = 0; j < 8; ++j)
#pragma unroll
            for (int p = 0; p < 4; ++p) {
                const u64 qi = C2(1.0f / Qt[2 * p][j], 1.0f / Qt[2 * p + 1][j]);
                const u64 qq = C2(Qt[2 * p][j], Qt[2 * p + 1][j]);
                u64 t = mul2(B[j][p], qi);
                t = sub2(add2(t, MAGIC), MAGIC);   // rint (RNE), |t| < 1 so exact
                B[j][p] = mul2(t, qq);
            }
    }

    // ---- row IDCT ----
#pragma unroll
    for (int p = 0; p < 4; ++p) {
        u64 v[8];
#pragma unroll
        for (int j = 0; j < 8; ++j) v[j] = B[j][p];
        idct8p(v);
#pragma unroll
        for (int j = 0; j < 8; ++j) B[j][p] = v[j];
    }

    // ---- repack B -> A ----
#pragma unroll
    for (int j = 0; j < 8; ++j)
#pragma unroll
        for (int p = 0; p < 4; ++p) upk(B[j][p], xf[2 * p][j], xf[2 * p + 1][j]);
#pragma unroll
    for (int i = 0; i < 8; ++i)
#pragma unroll
        for (int c = 0; c < 4; ++c) A[i][c] = pk(xf[i][2 * c], xf[i][2 * c + 1]);

    // ---- column IDCT ----
#pragma unroll
    for (int c = 0; c < 4; ++c) {
        u64 v[8];
#pragma unroll
        for (int i = 0; i < 8; ++i) v[i] = A[i][c];
        idct8p(v);
#pragma unroll
        for (int i = 0; i < 8; ++i) A[i][c] = v[i];
    }

    // ---- store (2x STG.128 per row) ----
#pragma unroll
    for (int i = 0; i < 8; ++i) {
        ulonglong2* pw = reinterpret_cast<ulonglong2*>(out + base + (size_t)i * IMG_W);
        ulonglong2 va, vb;
        va.x = A[i][0]; va.y = A[i][1]; vb.x = A[i][2]; vb.y = A[i][3];
        pw[0] = va;
        pw[1] = vb;
    }
}

extern "C" void kernel_launch(void* const* d_in, const int* in_sizes, int n_in,
                              void* d_out, int out_size)
{
    const float* img = (const float*)d_in[0];
    float* out = (float*)d_out;
    diffjpeg_kernel<<<NBLOCKS / TPB, TPB>>>(img, out);
}